// round 2
// baseline (speedup 1.0000x reference)
#include <cuda_runtime.h>
#include <cuda_bf16.h>
#include <math_constants.h>

// Problem shape (fixed by dataset)
#define NN 100000
#define NE 1600000
#define INF_ 128
#define OUTF 64

// ---------------- device scratch (static: no runtime allocation) -------------
__device__ float g_ft[(size_t)NN * OUTF];       // projected features  [N,64]
__device__ float g_a[NE];                       // raw edge scores
__device__ int   g_deg[NN];                     // in-degree histogram
__device__ int   g_offs[NN + 1];                // CSR offsets by dst
__device__ int   g_cursor[NN];                  // scatter cursors
__device__ int   g_csr_src[NE];                 // src node per CSR slot
__device__ float g_csr_a[NE];                   // score per CSR slot
__device__ int   g_bsum[1024];                  // scan block sums

// clamp node index into range (defense against dtype surprises; correct
// inputs are untouched)
__device__ __forceinline__ int clampidx(int v) {
    unsigned u = (unsigned)v;
    return (u < (unsigned)NN) ? v : 0;
}

// ---------------- K0: zero degree histogram ---------------------------------
__global__ void k_zero_deg() {
    int i = blockIdx.x * blockDim.x + threadIdx.x;
    if (i < NN) g_deg[i] = 0;
}

// ---------------- K1: ft = feat @ W  (fp32, smem-tiled) ----------------------
// 256 threads, tile = 32 rows x 64 cols; thread computes 2 rows x 4 cols.
__global__ __launch_bounds__(256) void k_gemm(const float* __restrict__ feat,
                                              const float* __restrict__ Wm) {
    __shared__ float wsm[INF_ * OUTF];   // 32 KB
    __shared__ float fsm[32 * INF_];     // 16 KB
    int tid = threadIdx.x;

    for (int i = tid; i < (INF_ * OUTF) / 4; i += 256)
        ((float4*)wsm)[i] = ((const float4*)Wm)[i];

    int row0 = blockIdx.x * 32;
    for (int i = tid; i < 32 * (INF_ / 4); i += 256) {
        int r = i >> 5;            // 0..31
        int k4 = i & 31;           // 0..31 float4 chunks
        int row = row0 + r;
        float4 v = make_float4(0.f, 0.f, 0.f, 0.f);
        if (row < NN) v = ((const float4*)(feat + (size_t)row * INF_))[k4];
        ((float4*)fsm)[r * 32 + k4] = v;
    }
    __syncthreads();

    int c0 = (tid & 15) * 4;       // output col group
    int r0 = (tid >> 4) * 2;       // output row pair
    const float* f0p = fsm + r0 * INF_;
    const float* f1p = fsm + (r0 + 1) * INF_;

    float4 acc0 = make_float4(0.f, 0.f, 0.f, 0.f);
    float4 acc1 = make_float4(0.f, 0.f, 0.f, 0.f);

#pragma unroll 4
    for (int k = 0; k < INF_; k++) {
        float4 w4 = *(const float4*)(wsm + k * OUTF + c0);
        float f0 = f0p[k];
        float f1 = f1p[k];
        acc0.x += f0 * w4.x; acc0.y += f0 * w4.y;
        acc0.z += f0 * w4.z; acc0.w += f0 * w4.w;
        acc1.x += f1 * w4.x; acc1.y += f1 * w4.y;
        acc1.z += f1 * w4.z; acc1.w += f1 * w4.w;
    }

    int row = row0 + r0;
    if (row < NN)     *(float4*)(g_ft + (size_t)row * OUTF + c0) = acc0;
    if (row + 1 < NN) *(float4*)(g_ft + (size_t)(row + 1) * OUTF + c0) = acc1;
}

// ---------------- K2: edge scores + degree histogram -------------------------
__global__ __launch_bounds__(256) void k_score(const int* __restrict__ src,
                                               const int* __restrict__ dst) {
    int e = blockIdx.x * blockDim.x + threadIdx.x;
    if (e >= NE) return;
    int s = clampidx(src[e]);
    int d = clampidx(dst[e]);
    const float4* fs = (const float4*)(g_ft + (size_t)s * OUTF);
    const float4* fd = (const float4*)(g_ft + (size_t)d * OUTF);
    float a0 = 0.f, a1 = 0.f, a2 = 0.f, a3 = 0.f;
#pragma unroll
    for (int i = 0; i < 16; i += 4) {
        float4 x0 = fs[i],     y0 = fd[i];
        float4 x1 = fs[i + 1], y1 = fd[i + 1];
        float4 x2 = fs[i + 2], y2 = fd[i + 2];
        float4 x3 = fs[i + 3], y3 = fd[i + 3];
        a0 += x0.x * y0.x + x0.y * y0.y + x0.z * y0.z + x0.w * y0.w;
        a1 += x1.x * y1.x + x1.y * y1.y + x1.z * y1.z + x1.w * y1.w;
        a2 += x2.x * y2.x + x2.y * y2.y + x2.z * y2.z + x2.w * y2.w;
        a3 += x3.x * y3.x + x3.y * y3.y + x3.z * y3.z + x3.w * y3.w;
    }
    g_a[e] = (a0 + a1) + (a2 + a3);
    atomicAdd(&g_deg[d], 1);
}

// ---------------- K3a/b/c: exclusive scan of degrees -> offsets --------------
__global__ __launch_bounds__(256) void k_scan1() {
    __shared__ int sm[256];
    int tid = threadIdx.x;
    int i = blockIdx.x * 256 + tid;
    int v = (i < NN) ? g_deg[i] : 0;
    sm[tid] = v;
    __syncthreads();
    for (int off = 1; off < 256; off <<= 1) {
        int t = (tid >= off) ? sm[tid - off] : 0;
        __syncthreads();
        sm[tid] += t;
        __syncthreads();
    }
    if (i < NN) g_offs[i] = sm[tid] - v;       // exclusive within block
    if (tid == 255) g_bsum[blockIdx.x] = sm[255];
}

__global__ __launch_bounds__(1024) void k_scan2(int nb) {
    __shared__ int sm[1024];
    int tid = threadIdx.x;
    int v = (tid < nb) ? g_bsum[tid] : 0;
    sm[tid] = v;
    __syncthreads();
    for (int off = 1; off < 1024; off <<= 1) {
        int t = (tid >= off) ? sm[tid - off] : 0;
        __syncthreads();
        sm[tid] += t;
        __syncthreads();
    }
    if (tid < nb) g_bsum[tid] = sm[tid] - v;   // exclusive
}

__global__ __launch_bounds__(256) void k_scan3() {
    int i = blockIdx.x * 256 + threadIdx.x;
    if (i < NN) {
        int o = g_offs[i] + g_bsum[i >> 8];
        g_offs[i] = o;
        g_cursor[i] = o;
    }
    if (i == 0) g_offs[NN] = NE;
}

// ---------------- K4: scatter edges into CSR order ---------------------------
__global__ __launch_bounds__(256) void k_scatter(const int* __restrict__ src,
                                                 const int* __restrict__ dst) {
    int e = blockIdx.x * blockDim.x + threadIdx.x;
    if (e >= NE) return;
    int d = clampidx(dst[e]);
    int p = atomicAdd(&g_cursor[d], 1);
    if (p < NE) {
        g_csr_src[p] = clampidx(src[e]);
        g_csr_a[p] = g_a[e];
    }
}

// ---------------- K5: per-node softmax + weighted aggregation ----------------
// One warp per node. Lane l owns output dims [2l, 2l+1].
__global__ __launch_bounds__(256) void k_aggregate(float* __restrict__ out) {
    int warp = (blockIdx.x * blockDim.x + threadIdx.x) >> 5;
    int lane = threadIdx.x & 31;
    if (warp >= NN) return;

    int lo = g_offs[warp];
    int hi = g_offs[warp + 1];

    // segment max (warp-strided then butterfly reduce)
    float m = -CUDART_INF_F;
    for (int i = lo + lane; i < hi; i += 32) m = fmaxf(m, g_csr_a[i]);
#pragma unroll
    for (int o = 16; o; o >>= 1) m = fmaxf(m, __shfl_xor_sync(0xffffffffu, m, o));

    // fused exp-sum + weighted feature accumulation (normalize at end)
    float s = 0.f;
    float2 acc = make_float2(0.f, 0.f);
#pragma unroll 4
    for (int i = lo; i < hi; i++) {
        float w = __expf(g_csr_a[i] - m);
        int sidx = g_csr_src[i];
        float2 f = *(const float2*)(g_ft + (size_t)sidx * OUTF + lane * 2);
        s += w;
        acc.x += w * f.x;
        acc.y += w * f.y;
    }
    if (hi > lo) {
        float inv = 1.f / s;
        acc.x *= inv;
        acc.y *= inv;
    }
    *(float2*)(out + (size_t)warp * OUTF + lane * 2) = acc;
}

// ---------------- launch ------------------------------------------------------
extern "C" void kernel_launch(void* const* d_in, const int* in_sizes, int n_in,
                              void* d_out, int out_size) {
    const float* feat = (const float*)d_in[0];
    const float* Wm   = (const float*)d_in[1];
    const int*   src  = (const int*)d_in[2];
    const int*   dst  = (const int*)d_in[3];
    float* out = (float*)d_out;

    int nbN = (NN + 255) / 256;            // 391
    int nbE = (NE + 255) / 256;            // 6250
    int nbG = (NN + 31) / 32;              // 3125
    int nbA = (NN * 32 + 255) / 256;       // 12500

    k_zero_deg<<<nbN, 256>>>();
    k_gemm<<<nbG, 256>>>(feat, Wm);
    k_score<<<nbE, 256>>>(src, dst);
    k_scan1<<<nbN, 256>>>();
    k_scan2<<<1, 1024>>>(nbN);
    k_scan3<<<nbN, 256>>>();
    k_scatter<<<nbE, 256>>>(src, dst);
    k_aggregate<<<nbA, 256>>>(out);
}

// round 3
// speedup vs baseline: 1.6160x; 1.6160x over previous
#include <cuda_runtime.h>
#include <cuda_bf16.h>
#include <math_constants.h>

// Problem shape (fixed by dataset)
#define NN 100000
#define NE 1600000
#define INF_ 128
#define OUTF 64

// ---------------- device scratch (static: no runtime allocation) -------------
__device__ float g_ft[(size_t)NN * OUTF];       // projected features  [N,64]
__device__ int   g_deg[NN];                     // in-degree histogram
__device__ int   g_offs[NN + 1];                // CSR offsets by dst
__device__ int   g_cursor[NN];                  // scatter cursors
__device__ int   g_csr_src[NE];                 // src node per CSR slot
__device__ float g_csr_a[NE];                   // score spill (deg>128 fallback)
__device__ int   g_bsum[1024];                  // scan block sums

__device__ __forceinline__ int clampidx(int v) {
    unsigned u = (unsigned)v;
    return (u < (unsigned)NN) ? v : 0;
}

// ---------------- K0: zero degree histogram ---------------------------------
__global__ void k_zero_deg() {
    int i = blockIdx.x * blockDim.x + threadIdx.x;
    if (i < NN) g_deg[i] = 0;
}

// ---------------- K1: in-degree histogram (int4 vectorized) ------------------
__global__ __launch_bounds__(256) void k_deg(const int* __restrict__ dst) {
    int t = blockIdx.x * blockDim.x + threadIdx.x;
    if (t >= NE / 4) return;
    int4 d4 = ((const int4*)dst)[t];
    atomicAdd(&g_deg[clampidx(d4.x)], 1);
    atomicAdd(&g_deg[clampidx(d4.y)], 1);
    atomicAdd(&g_deg[clampidx(d4.z)], 1);
    atomicAdd(&g_deg[clampidx(d4.w)], 1);
}

// ---------------- K2a/b/c: exclusive scan of degrees -> offsets --------------
__global__ __launch_bounds__(256) void k_scan1() {
    __shared__ int sm[256];
    int tid = threadIdx.x;
    int i = blockIdx.x * 256 + tid;
    int v = (i < NN) ? g_deg[i] : 0;
    sm[tid] = v;
    __syncthreads();
    for (int off = 1; off < 256; off <<= 1) {
        int t = (tid >= off) ? sm[tid - off] : 0;
        __syncthreads();
        sm[tid] += t;
        __syncthreads();
    }
    if (i < NN) g_offs[i] = sm[tid] - v;       // exclusive within block
    if (tid == 255) g_bsum[blockIdx.x] = sm[255];
}

__global__ __launch_bounds__(1024) void k_scan2(int nb) {
    __shared__ int sm[1024];
    int tid = threadIdx.x;
    int v = (tid < nb) ? g_bsum[tid] : 0;
    sm[tid] = v;
    __syncthreads();
    for (int off = 1; off < 1024; off <<= 1) {
        int t = (tid >= off) ? sm[tid - off] : 0;
        __syncthreads();
        sm[tid] += t;
        __syncthreads();
    }
    if (tid < nb) g_bsum[tid] = sm[tid] - v;   // exclusive
}

__global__ __launch_bounds__(256) void k_scan3() {
    int i = blockIdx.x * 256 + threadIdx.x;
    if (i < NN) {
        int o = g_offs[i] + g_bsum[i >> 8];
        g_offs[i] = o;
        g_cursor[i] = o;
    }
    if (i == 0) g_offs[NN] = NE;
}

// ---------------- K3: scatter edges into CSR order (int4 vectorized) ---------
__global__ __launch_bounds__(256) void k_scatter(const int* __restrict__ src,
                                                 const int* __restrict__ dst) {
    int t = blockIdx.x * blockDim.x + threadIdx.x;
    if (t >= NE / 4) return;
    int4 s4 = ((const int4*)src)[t];
    int4 d4 = ((const int4*)dst)[t];
    int p;
    p = atomicAdd(&g_cursor[clampidx(d4.x)], 1); g_csr_src[p] = clampidx(s4.x);
    p = atomicAdd(&g_cursor[clampidx(d4.y)], 1); g_csr_src[p] = clampidx(s4.y);
    p = atomicAdd(&g_cursor[clampidx(d4.z)], 1); g_csr_src[p] = clampidx(s4.z);
    p = atomicAdd(&g_cursor[clampidx(d4.w)], 1); g_csr_src[p] = clampidx(s4.w);
}

// ---------------- K4: ft = feat @ W  (fp32, smem-tiled) ----------------------
// 256 threads, tile = 32 rows x 64 cols; thread computes 2 rows x 4 cols.
__global__ __launch_bounds__(256) void k_gemm(const float* __restrict__ feat,
                                              const float* __restrict__ Wm) {
    __shared__ float wsm[INF_ * OUTF];   // 32 KB
    __shared__ float fsm[32 * INF_];     // 16 KB
    int tid = threadIdx.x;

    for (int i = tid; i < (INF_ * OUTF) / 4; i += 256)
        ((float4*)wsm)[i] = ((const float4*)Wm)[i];

    int row0 = blockIdx.x * 32;
    for (int i = tid; i < 32 * (INF_ / 4); i += 256) {
        int r = i >> 5;            // 0..31
        int k4 = i & 31;           // 0..31 float4 chunks
        int row = row0 + r;
        float4 v = make_float4(0.f, 0.f, 0.f, 0.f);
        if (row < NN) v = ((const float4*)(feat + (size_t)row * INF_))[k4];
        ((float4*)fsm)[r * 32 + k4] = v;
    }
    __syncthreads();

    int c0 = (tid & 15) * 4;       // output col group
    int r0 = (tid >> 4) * 2;       // output row pair
    const float* f0p = fsm + r0 * INF_;
    const float* f1p = fsm + (r0 + 1) * INF_;

    float4 acc0 = make_float4(0.f, 0.f, 0.f, 0.f);
    float4 acc1 = make_float4(0.f, 0.f, 0.f, 0.f);

#pragma unroll 4
    for (int k = 0; k < INF_; k++) {
        float4 w4 = *(const float4*)(wsm + k * OUTF + c0);
        float f0 = f0p[k];
        float f1 = f1p[k];
        acc0.x += f0 * w4.x; acc0.y += f0 * w4.y;
        acc0.z += f0 * w4.z; acc0.w += f0 * w4.w;
        acc1.x += f1 * w4.x; acc1.y += f1 * w4.y;
        acc1.z += f1 * w4.z; acc1.w += f1 * w4.w;
    }

    int row = row0 + r0;
    if (row < NN)     *(float4*)(g_ft + (size_t)row * OUTF + c0) = acc0;
    if (row + 1 < NN) *(float4*)(g_ft + (size_t)(row + 1) * OUTF + c0) = acc1;
}

// ---------------- K5: fused score + softmax + weighted aggregation -----------
// One warp per node; lane l owns output dims [2l, 2l+1].
// Pass 1: coalesced gather ft[src], dot with register-resident ft[dst] via
//         butterfly reduce (2-edge interleaved). Scores cached in smem.
// Pass 2: re-gather ft[src], w = exp(a - m), accumulate; normalize at end.
#define ABUF_CAP 128
__global__ __launch_bounds__(256) void k_aggregate(float* __restrict__ out) {
    __shared__ float abuf[8][ABUF_CAP];
    int w = threadIdx.x >> 5;
    int lane = threadIdx.x & 31;
    int node = blockIdx.x * 8 + w;
    if (node >= NN) return;

    int lo = g_offs[node];
    int hi = g_offs[node + 1];
    int n = hi - lo;

    // dst feature (register resident)
    float2 df = *(const float2*)(g_ft + (size_t)node * OUTF + lane * 2);

    // score buffer: smem if it fits, global spill otherwise
    float* ap = (n <= ABUF_CAP) ? (abuf[w] - lo) : g_csr_a;

    // ---- pass 1: scores + max -------------------------------------------
    float m = -CUDART_INF_F;
    int i = lo;
    for (; i + 1 < hi; i += 2) {
        int s0 = g_csr_src[i];
        int s1 = g_csr_src[i + 1];
        float2 f0 = *(const float2*)(g_ft + (size_t)s0 * OUTF + lane * 2);
        float2 f1 = *(const float2*)(g_ft + (size_t)s1 * OUTF + lane * 2);
        float p0 = f0.x * df.x + f0.y * df.y;
        float p1 = f1.x * df.x + f1.y * df.y;
#pragma unroll
        for (int o = 16; o; o >>= 1) {
            p0 += __shfl_xor_sync(0xffffffffu, p0, o);
            p1 += __shfl_xor_sync(0xffffffffu, p1, o);
        }
        if (lane == 0) { ap[i] = p0; ap[i + 1] = p1; }
        m = fmaxf(m, fmaxf(p0, p1));
    }
    if (i < hi) {
        int s0 = g_csr_src[i];
        float2 f0 = *(const float2*)(g_ft + (size_t)s0 * OUTF + lane * 2);
        float p0 = f0.x * df.x + f0.y * df.y;
#pragma unroll
        for (int o = 16; o; o >>= 1) p0 += __shfl_xor_sync(0xffffffffu, p0, o);
        if (lane == 0) ap[i] = p0;
        m = fmaxf(m, p0);
    }
    __syncwarp();

    // ---- pass 2: exp + weighted accumulation ----------------------------
    float s = 0.f;
    float2 acc = make_float2(0.f, 0.f);
    for (int j = lo; j < hi; j++) {
        float wgt = __expf(ap[j] - m);
        int sidx = g_csr_src[j];
        float2 f = *(const float2*)(g_ft + (size_t)sidx * OUTF + lane * 2);
        s += wgt;
        acc.x += wgt * f.x;
        acc.y += wgt * f.y;
    }
    if (n > 0) {
        float inv = 1.f / s;
        acc.x *= inv;
        acc.y *= inv;
    }
    *(float2*)(out + (size_t)node * OUTF + lane * 2) = acc;
}

// ---------------- launch ------------------------------------------------------
extern "C" void kernel_launch(void* const* d_in, const int* in_sizes, int n_in,
                              void* d_out, int out_size) {
    const float* feat = (const float*)d_in[0];
    const float* Wm   = (const float*)d_in[1];
    const int*   src  = (const int*)d_in[2];
    const int*   dst  = (const int*)d_in[3];
    float* out = (float*)d_out;

    int nbN  = (NN + 255) / 256;             // 391
    int nbE4 = (NE / 4 + 255) / 256;         // 1563
    int nbG  = (NN + 31) / 32;               // 3125
    int nbA  = (NN + 7) / 8;                 // 12500

    k_zero_deg<<<nbN, 256>>>();
    k_deg<<<nbE4, 256>>>(dst);
    k_scan1<<<nbN, 256>>>();
    k_scan2<<<1, 1024>>>(nbN);
    k_scan3<<<nbN, 256>>>();
    k_scatter<<<nbE4, 256>>>(src, dst);
    k_gemm<<<nbG, 256>>>(feat, Wm);
    k_aggregate<<<nbA, 256>>>(out);
}

// round 4
// speedup vs baseline: 1.9364x; 1.1983x over previous
#include <cuda_runtime.h>
#include <cuda_bf16.h>
#include <math_constants.h>

// Problem shape (fixed by dataset)
#define NN 100000
#define NE 1600000
#define INF_ 128
#define OUTF 64

// ---------------- device scratch (static: no runtime allocation) -------------
__device__ float g_ft[(size_t)NN * OUTF];       // projected features  [N,64]
__device__ int   g_deg[NN];                     // in-degree histogram
__device__ int   g_offs[NN + 1];                // CSR offsets by dst
__device__ int   g_cursor[NN];                  // scatter cursors
__device__ int   g_csr_src[NE];                 // src node per CSR slot
__device__ int   g_bsum[1024];                  // scan block sums

__device__ __forceinline__ int clampidx(int v) {
    unsigned u = (unsigned)v;
    return (u < (unsigned)NN) ? v : 0;
}

// packed f32x2 helpers (Blackwell: FFMA2 only reachable from PTX)
__device__ __forceinline__ unsigned long long pack2(float lo, float hi) {
    unsigned long long r;
    asm("mov.b64 %0, {%1, %2};" : "=l"(r) : "f"(lo), "f"(hi));
    return r;
}
__device__ __forceinline__ void unpack2(unsigned long long v, float& lo, float& hi) {
    asm("mov.b64 {%0, %1}, %2;" : "=f"(lo), "=f"(hi) : "l"(v));
}
__device__ __forceinline__ void fma2(unsigned long long& d,
                                     unsigned long long a, unsigned long long b) {
    asm("fma.rn.f32x2 %0, %1, %2, %0;" : "+l"(d) : "l"(a), "l"(b));
}

// ---------------- K0: zero degree histogram ---------------------------------
__global__ void k_zero_deg() {
    int i = blockIdx.x * blockDim.x + threadIdx.x;
    if (i < NN) g_deg[i] = 0;
}

// ---------------- K1: in-degree histogram (int4 vectorized) ------------------
__global__ __launch_bounds__(256) void k_deg(const int* __restrict__ dst) {
    int t = blockIdx.x * blockDim.x + threadIdx.x;
    if (t >= NE / 4) return;
    int4 d4 = ((const int4*)dst)[t];
    atomicAdd(&g_deg[clampidx(d4.x)], 1);
    atomicAdd(&g_deg[clampidx(d4.y)], 1);
    atomicAdd(&g_deg[clampidx(d4.z)], 1);
    atomicAdd(&g_deg[clampidx(d4.w)], 1);
}

// ---------------- K2a/b/c: exclusive scan of degrees -> offsets --------------
__global__ __launch_bounds__(256) void k_scan1() {
    __shared__ int sm[256];
    int tid = threadIdx.x;
    int i = blockIdx.x * 256 + tid;
    int v = (i < NN) ? g_deg[i] : 0;
    sm[tid] = v;
    __syncthreads();
    for (int off = 1; off < 256; off <<= 1) {
        int t = (tid >= off) ? sm[tid - off] : 0;
        __syncthreads();
        sm[tid] += t;
        __syncthreads();
    }
    if (i < NN) g_offs[i] = sm[tid] - v;       // exclusive within block
    if (tid == 255) g_bsum[blockIdx.x] = sm[255];
}

// shuffle-based scan over <=512 block sums (2 barriers)
__global__ __launch_bounds__(512) void k_scan2(int nb) {
    __shared__ int ws[16];
    int tid = threadIdx.x;
    int lane = tid & 31;
    int wid = tid >> 5;
    int v = (tid < nb) ? g_bsum[tid] : 0;
    int x = v;
#pragma unroll
    for (int o = 1; o < 32; o <<= 1) {
        int t = __shfl_up_sync(0xffffffffu, x, o);
        if (lane >= o) x += t;
    }
    if (lane == 31) ws[wid] = x;
    __syncthreads();
    if (wid == 0) {
        int y = (lane < 16) ? ws[lane] : 0;
#pragma unroll
        for (int o = 1; o < 16; o <<= 1) {
            int t = __shfl_up_sync(0xffffffffu, y, o);
            if (lane >= o) y += t;
        }
        if (lane < 16) ws[lane] = y;
    }
    __syncthreads();
    int off = (wid > 0) ? ws[wid - 1] : 0;
    if (tid < nb) g_bsum[tid] = off + x - v;   // exclusive
}

__global__ __launch_bounds__(256) void k_scan3() {
    int i = blockIdx.x * 256 + threadIdx.x;
    if (i < NN) {
        int o = g_offs[i] + g_bsum[i >> 8];
        g_offs[i] = o;
        g_cursor[i] = o;
    }
    if (i == 0) g_offs[NN] = NE;
}

// ---------------- K3: scatter edges into CSR order (int4 vectorized) ---------
__global__ __launch_bounds__(256) void k_scatter(const int* __restrict__ src,
                                                 const int* __restrict__ dst) {
    int t = blockIdx.x * blockDim.x + threadIdx.x;
    if (t >= NE / 4) return;
    int4 s4 = ((const int4*)src)[t];
    int4 d4 = ((const int4*)dst)[t];
    int p;
    p = atomicAdd(&g_cursor[clampidx(d4.x)], 1); g_csr_src[p] = clampidx(s4.x);
    p = atomicAdd(&g_cursor[clampidx(d4.y)], 1); g_csr_src[p] = clampidx(s4.y);
    p = atomicAdd(&g_cursor[clampidx(d4.z)], 1); g_csr_src[p] = clampidx(s4.z);
    p = atomicAdd(&g_cursor[clampidx(d4.w)], 1); g_csr_src[p] = clampidx(s4.w);
}

// ---------------- K4: ft = feat @ W  (64x64 tile, f32x2 FFMA2) ---------------
// 256 threads; thread computes 4 rows x 4 cols. W staged in smem (32 KB);
// feat read directly from global (L2-resident, broadcast-coalesced LDG.128).
__global__ __launch_bounds__(256) void k_gemm(const float* __restrict__ feat,
                                              const float* __restrict__ Wm) {
    __shared__ float wsm[INF_ * OUTF];   // 32 KB
    int tid = threadIdx.x;

    for (int i = tid; i < (INF_ * OUTF) / 4; i += 256)
        ((float4*)wsm)[i] = ((const float4*)Wm)[i];
    __syncthreads();

    int row0 = blockIdx.x * 64 + (tid >> 4) * 4;   // 4 rows
    int c0 = (tid & 15) * 4;                       // 4 cols

    // clamp read rows (stores are guarded)
    int r[4];
#pragma unroll
    for (int i = 0; i < 4; i++) r[i] = (row0 + i < NN) ? row0 + i : 0;

    // acc[row][colpair] as packed f32x2
    unsigned long long acc[4][2];
#pragma unroll
    for (int i = 0; i < 4; i++) { acc[i][0] = 0ull; acc[i][1] = 0ull; }

#pragma unroll 2
    for (int kk = 0; kk < INF_ / 4; kk++) {
        float4 fr[4];
#pragma unroll
        for (int i = 0; i < 4; i++)
            fr[i] = ((const float4*)(feat + (size_t)r[i] * INF_))[kk];
#pragma unroll
        for (int j = 0; j < 4; j++) {
            float4 w4 = *(const float4*)(wsm + (kk * 4 + j) * OUTF + c0);
            unsigned long long bxy = pack2(w4.x, w4.y);
            unsigned long long bzw = pack2(w4.z, w4.w);
#pragma unroll
            for (int i = 0; i < 4; i++) {
                float f = (j == 0) ? fr[i].x : (j == 1) ? fr[i].y
                         : (j == 2) ? fr[i].z : fr[i].w;
                unsigned long long a2 = pack2(f, f);
                fma2(acc[i][0], a2, bxy);
                fma2(acc[i][1], a2, bzw);
            }
        }
    }

#pragma unroll
    for (int i = 0; i < 4; i++) {
        int row = row0 + i;
        if (row < NN) {
            float4 o;
            unpack2(acc[i][0], o.x, o.y);
            unpack2(acc[i][1], o.z, o.w);
            *(float4*)(g_ft + (size_t)row * OUTF + c0) = o;
        }
    }
}

// ---------------- K5: fused score + ONLINE softmax + aggregation -------------
// One warp per node; lane l owns output dims [2l, 2l+1]. Single pass over the
// node's edges: gather ft[src] (coalesced, 256B/edge), dot with register-
// resident ft[dst] via butterfly reduce, flash-style online (m, s, acc).
__global__ __launch_bounds__(256) void k_aggregate(float* __restrict__ out) {
    int w = threadIdx.x >> 5;
    int lane = threadIdx.x & 31;
    int node = blockIdx.x * 8 + w;
    if (node >= NN) return;

    int lo = g_offs[node];
    int hi = g_offs[node + 1];

    float2 df = *(const float2*)(g_ft + (size_t)node * OUTF + lane * 2);

    float m = -CUDART_INF_F;
    float s = 0.f;
    float2 acc = make_float2(0.f, 0.f);

    int i = lo;
    for (; i + 1 < hi; i += 2) {
        int s0 = g_csr_src[i];
        int s1 = g_csr_src[i + 1];
        float2 f0 = *(const float2*)(g_ft + (size_t)s0 * OUTF + lane * 2);
        float2 f1 = *(const float2*)(g_ft + (size_t)s1 * OUTF + lane * 2);
        float p0 = f0.x * df.x + f0.y * df.y;
        float p1 = f1.x * df.x + f1.y * df.y;
#pragma unroll
        for (int o = 16; o; o >>= 1) {
            p0 += __shfl_xor_sync(0xffffffffu, p0, o);
            p1 += __shfl_xor_sync(0xffffffffu, p1, o);
        }
        float mn = fmaxf(p0, p1);
        if (mn > m) {                          // warp-uniform branch
            float rsc = __expf(m - mn);        // first hit: exp(-inf)=0
            s *= rsc; acc.x *= rsc; acc.y *= rsc;
            m = mn;
        }
        float w0 = __expf(p0 - m);
        float w1 = __expf(p1 - m);
        s += w0 + w1;
        acc.x += w0 * f0.x + w1 * f1.x;
        acc.y += w0 * f0.y + w1 * f1.y;
    }
    if (i < hi) {
        int s0 = g_csr_src[i];
        float2 f0 = *(const float2*)(g_ft + (size_t)s0 * OUTF + lane * 2);
        float p0 = f0.x * df.x + f0.y * df.y;
#pragma unroll
        for (int o = 16; o; o >>= 1) p0 += __shfl_xor_sync(0xffffffffu, p0, o);
        if (p0 > m) {
            float rsc = __expf(m - p0);
            s *= rsc; acc.x *= rsc; acc.y *= rsc;
            m = p0;
        }
        float w0 = __expf(p0 - m);
        s += w0;
        acc.x += w0 * f0.x;
        acc.y += w0 * f0.y;
    }

    if (hi > lo) {
        float inv = 1.f / s;
        acc.x *= inv;
        acc.y *= inv;
    }
    *(float2*)(out + (size_t)node * OUTF + lane * 2) = acc;
}

// ---------------- launch ------------------------------------------------------
extern "C" void kernel_launch(void* const* d_in, const int* in_sizes, int n_in,
                              void* d_out, int out_size) {
    const float* feat = (const float*)d_in[0];
    const float* Wm   = (const float*)d_in[1];
    const int*   src  = (const int*)d_in[2];
    const int*   dst  = (const int*)d_in[3];
    float* out = (float*)d_out;

    int nbN  = (NN + 255) / 256;             // 391
    int nbE4 = (NE / 4 + 255) / 256;         // 1563
    int nbG  = (NN + 63) / 64;               // 1563
    int nbA  = (NN + 7) / 8;                 // 12500

    k_zero_deg<<<nbN, 256>>>();
    k_deg<<<nbE4, 256>>>(dst);
    k_scan1<<<nbN, 256>>>();
    k_scan2<<<1, 512>>>(nbN);
    k_scan3<<<nbN, 256>>>();
    k_scatter<<<nbE4, 256>>>(src, dst);
    k_gemm<<<nbG, 256>>>(feat, Wm);
    k_aggregate<<<nbA, 256>>>(out);
}

// round 5
// speedup vs baseline: 1.9530x; 1.0086x over previous
#include <cuda_runtime.h>
#include <cuda_bf16.h>
#include <math_constants.h>

// Problem shape (fixed by dataset)
#define NN 100000
#define NE 1600000
#define INF_ 128
#define OUTF 64
#define SCAN_NB 391          // ceil(NN/256)

// ---------------- device scratch (static: no runtime allocation) -------------
__device__ float g_ft[(size_t)NN * OUTF];       // projected features  [N,64]
__device__ int   g_deg[NN];                     // in-degree histogram
__device__ int   g_offs[NN + 1];                // CSR offsets by dst
__device__ int   g_cursor[NN];                  // scatter cursors
__device__ int   g_csr_src[NE];                 // src node per CSR slot
__device__ unsigned long long g_state[SCAN_NB]; // lookback: (status<<32)|sum

__device__ __forceinline__ int clampidx(int v) {
    unsigned u = (unsigned)v;
    return (u < (unsigned)NN) ? v : 0;
}

// packed f32x2 helpers (Blackwell: FFMA2 only reachable from PTX)
__device__ __forceinline__ unsigned long long pack2(float lo, float hi) {
    unsigned long long r;
    asm("mov.b64 %0, {%1, %2};" : "=l"(r) : "f"(lo), "f"(hi));
    return r;
}
__device__ __forceinline__ void unpack2(unsigned long long v, float& lo, float& hi) {
    asm("mov.b64 {%0, %1}, %2;" : "=f"(lo), "=f"(hi) : "l"(v));
}
__device__ __forceinline__ void fma2(unsigned long long& d,
                                     unsigned long long a, unsigned long long b) {
    asm("fma.rn.f32x2 %0, %1, %2, %0;" : "+l"(d) : "l"(a), "l"(b));
}

// ---------------- K0: zero degree histogram + scan state ---------------------
__global__ void k_zero() {
    int i = blockIdx.x * blockDim.x + threadIdx.x;
    if (i < NN) g_deg[i] = 0;
    if (i < SCAN_NB) g_state[i] = 0ull;
}

// ---------------- K1: in-degree histogram (int4 vectorized) ------------------
__global__ __launch_bounds__(256) void k_deg(const int* __restrict__ dst) {
    int t = blockIdx.x * blockDim.x + threadIdx.x;
    if (t >= NE / 4) return;
    int4 d4 = ((const int4*)dst)[t];
    atomicAdd(&g_deg[clampidx(d4.x)], 1);
    atomicAdd(&g_deg[clampidx(d4.y)], 1);
    atomicAdd(&g_deg[clampidx(d4.z)], 1);
    atomicAdd(&g_deg[clampidx(d4.w)], 1);
}

// ---------------- K2: single-pass decoupled-lookback exclusive scan ----------
// 391 blocks x 256 threads. Status packed with value in one 64-bit word:
// status 0 = invalid, 1 = block aggregate, 2 = inclusive prefix.
__global__ __launch_bounds__(256) void k_scan() {
    __shared__ int wsum[8];
    __shared__ int bprefix;
    int b = blockIdx.x;
    int tid = threadIdx.x;
    int lane = tid & 31;
    int wid = tid >> 5;
    int i = b * 256 + tid;

    int v = (i < NN) ? g_deg[i] : 0;
    // warp inclusive scan
    int x = v;
#pragma unroll
    for (int o = 1; o < 32; o <<= 1) {
        int t = __shfl_up_sync(0xffffffffu, x, o);
        if (lane >= o) x += t;
    }
    if (lane == 31) wsum[wid] = x;
    __syncthreads();
    if (wid == 0) {
        int y = (lane < 8) ? wsum[lane] : 0;
#pragma unroll
        for (int o = 1; o < 8; o <<= 1) {
            int t = __shfl_up_sync(0xffffffffu, y, o);
            if (lane >= o) y += t;
        }
        if (lane < 8) wsum[lane] = y;
    }
    __syncthreads();
    int incl = x + ((wid > 0) ? wsum[wid - 1] : 0);   // block-local inclusive
    int btotal = wsum[7];

    if (tid == 0) {
        if (b == 0) {
            atomicExch(&g_state[0], (2ull << 32) | (unsigned)btotal);
            bprefix = 0;
        } else {
            atomicExch(&g_state[b], (1ull << 32) | (unsigned)btotal);
            // lookback
            long long ex = 0;
            int pred = b - 1;
            while (true) {
                unsigned long long s =
                    *((volatile unsigned long long*)&g_state[pred]);
                unsigned st = (unsigned)(s >> 32);
                if (st == 0) continue;            // spin
                ex += (unsigned)s;
                if (st == 2) break;
                pred--;
            }
            atomicExch(&g_state[b], (2ull << 32) | (unsigned)(ex + btotal));
            bprefix = (int)ex;
        }
    }
    __syncthreads();

    if (i < NN) {
        int o = bprefix + incl - v;               // exclusive
        g_offs[i] = o;
        g_cursor[i] = o;
    }
    if (i == 0) g_offs[NN] = NE;
}

// ---------------- K3: scatter edges into CSR order (int4 vectorized) ---------
__global__ __launch_bounds__(256) void k_scatter(const int* __restrict__ src,
                                                 const int* __restrict__ dst) {
    int t = blockIdx.x * blockDim.x + threadIdx.x;
    if (t >= NE / 4) return;
    int4 s4 = ((const int4*)src)[t];
    int4 d4 = ((const int4*)dst)[t];
    int p;
    p = atomicAdd(&g_cursor[clampidx(d4.x)], 1); g_csr_src[p] = clampidx(s4.x);
    p = atomicAdd(&g_cursor[clampidx(d4.y)], 1); g_csr_src[p] = clampidx(s4.y);
    p = atomicAdd(&g_cursor[clampidx(d4.z)], 1); g_csr_src[p] = clampidx(s4.z);
    p = atomicAdd(&g_cursor[clampidx(d4.w)], 1); g_csr_src[p] = clampidx(s4.w);
}

// ---------------- K4: ft = feat @ W  (64x64 tile, f32x2 FFMA2) ---------------
__global__ __launch_bounds__(256) void k_gemm(const float* __restrict__ feat,
                                              const float* __restrict__ Wm) {
    __shared__ float wsm[INF_ * OUTF];   // 32 KB
    int tid = threadIdx.x;

    for (int i = tid; i < (INF_ * OUTF) / 4; i += 256)
        ((float4*)wsm)[i] = ((const float4*)Wm)[i];
    __syncthreads();

    int row0 = blockIdx.x * 64 + (tid >> 4) * 4;   // 4 rows
    int c0 = (tid & 15) * 4;                       // 4 cols

    int r[4];
#pragma unroll
    for (int i = 0; i < 4; i++) r[i] = (row0 + i < NN) ? row0 + i : 0;

    unsigned long long acc[4][2];
#pragma unroll
    for (int i = 0; i < 4; i++) { acc[i][0] = 0ull; acc[i][1] = 0ull; }

#pragma unroll 2
    for (int kk = 0; kk < INF_ / 4; kk++) {
        float4 fr[4];
#pragma unroll
        for (int i = 0; i < 4; i++)
            fr[i] = ((const float4*)(feat + (size_t)r[i] * INF_))[kk];
#pragma unroll
        for (int j = 0; j < 4; j++) {
            float4 w4 = *(const float4*)(wsm + (kk * 4 + j) * OUTF + c0);
            unsigned long long bxy = pack2(w4.x, w4.y);
            unsigned long long bzw = pack2(w4.z, w4.w);
#pragma unroll
            for (int i = 0; i < 4; i++) {
                float f = (j == 0) ? fr[i].x : (j == 1) ? fr[i].y
                         : (j == 2) ? fr[i].z : fr[i].w;
                unsigned long long a2 = pack2(f, f);
                fma2(acc[i][0], a2, bxy);
                fma2(acc[i][1], a2, bzw);
            }
        }
    }

#pragma unroll
    for (int i = 0; i < 4; i++) {
        int row = row0 + i;
        if (row < NN) {
            float4 o;
            unpack2(acc[i][0], o.x, o.y);
            unpack2(acc[i][1], o.z, o.w);
            *(float4*)(g_ft + (size_t)row * OUTF + c0) = o;
        }
    }
}

// ---------------- K5: fused score + ONLINE softmax + aggregation -------------
// One warp per node; lane l owns output dims [2l, 2l+1].
// Warp dot-reduce via half-warp fold: 6 SHFLs per 2 edges (vs 10 butterfly).
// Two independent fold chains -> 4 edges/iter, MLP=4 on the gathers.
__global__ __launch_bounds__(256) void k_aggregate(float* __restrict__ out) {
    int w = threadIdx.x >> 5;
    int lane = threadIdx.x & 31;
    int node = blockIdx.x * 8 + w;
    if (node >= NN) return;

    int lo = g_offs[node];
    int hi = g_offs[node + 1];

    float2 df = *(const float2*)(g_ft + (size_t)node * OUTF + lane * 2);

    float m = -CUDART_INF_F;
    float s = 0.f;
    float2 acc = make_float2(0.f, 0.f);
    bool hi16 = (lane & 16) != 0;

    int i = lo;
    for (; i + 3 < hi; i += 4) {
        int s0 = g_csr_src[i];
        int s1 = g_csr_src[i + 1];
        int s2 = g_csr_src[i + 2];
        int s3 = g_csr_src[i + 3];
        float2 f0 = *(const float2*)(g_ft + (size_t)s0 * OUTF + lane * 2);
        float2 f1 = *(const float2*)(g_ft + (size_t)s1 * OUTF + lane * 2);
        float2 f2 = *(const float2*)(g_ft + (size_t)s2 * OUTF + lane * 2);
        float2 f3 = *(const float2*)(g_ft + (size_t)s3 * OUTF + lane * 2);
        float p0 = f0.x * df.x + f0.y * df.y;
        float p1 = f1.x * df.x + f1.y * df.y;
        float p2 = f2.x * df.x + f2.y * df.y;
        float p3 = f3.x * df.x + f3.y * df.y;

        // fold chains: low half reduces even edge, high half odd edge
        float uA = hi16 ? p1 : p0;
        float uB = hi16 ? p3 : p2;
        uA += __shfl_xor_sync(0xffffffffu, hi16 ? p0 : p1, 16);
        uB += __shfl_xor_sync(0xffffffffu, hi16 ? p2 : p3, 16);
#pragma unroll
        for (int o = 8; o; o >>= 1) {
            uA += __shfl_xor_sync(0xffffffffu, uA, o);
            uB += __shfl_xor_sync(0xffffffffu, uB, o);
        }
        float oA = __shfl_xor_sync(0xffffffffu, uA, 16);
        float oB = __shfl_xor_sync(0xffffffffu, uB, 16);
        float a0 = hi16 ? oA : uA;
        float a1 = hi16 ? uA : oA;
        float a2 = hi16 ? oB : uB;
        float a3 = hi16 ? uB : oB;

        float mn = fmaxf(fmaxf(a0, a1), fmaxf(a2, a3));
        if (mn > m) {                          // warp-uniform branch
            float rsc = __expf(m - mn);        // first hit: exp(-inf)=0
            s *= rsc; acc.x *= rsc; acc.y *= rsc;
            m = mn;
        }
        float w0 = __expf(a0 - m);
        float w1 = __expf(a1 - m);
        float w2 = __expf(a2 - m);
        float w3 = __expf(a3 - m);
        s += (w0 + w1) + (w2 + w3);
        acc.x += w0 * f0.x + w1 * f1.x + w2 * f2.x + w3 * f3.x;
        acc.y += w0 * f0.y + w1 * f1.y + w2 * f2.y + w3 * f3.y;
    }
    // remainder (0-3 edges): plain butterfly
    for (; i < hi; i++) {
        int s0 = g_csr_src[i];
        float2 f0 = *(const float2*)(g_ft + (size_t)s0 * OUTF + lane * 2);
        float p0 = f0.x * df.x + f0.y * df.y;
#pragma unroll
        for (int o = 16; o; o >>= 1) p0 += __shfl_xor_sync(0xffffffffu, p0, o);
        if (p0 > m) {
            float rsc = __expf(m - p0);
            s *= rsc; acc.x *= rsc; acc.y *= rsc;
            m = p0;
        }
        float w0 = __expf(p0 - m);
        s += w0;
        acc.x += w0 * f0.x;
        acc.y += w0 * f0.y;
    }

    if (hi > lo) {
        float inv = 1.f / s;
        acc.x *= inv;
        acc.y *= inv;
    }
    *(float2*)(out + (size_t)node * OUTF + lane * 2) = acc;
}

// ---------------- launch ------------------------------------------------------
extern "C" void kernel_launch(void* const* d_in, const int* in_sizes, int n_in,
                              void* d_out, int out_size) {
    const float* feat = (const float*)d_in[0];
    const float* Wm   = (const float*)d_in[1];
    const int*   src  = (const int*)d_in[2];
    const int*   dst  = (const int*)d_in[3];
    float* out = (float*)d_out;

    int nbN  = (NN + 255) / 256;             // 391
    int nbE4 = (NE / 4 + 255) / 256;         // 1563
    int nbG  = (NN + 63) / 64;               // 1563
    int nbA  = (NN + 7) / 8;                 // 12500

    k_zero<<<nbN, 256>>>();
    k_deg<<<nbE4, 256>>>(dst);
    k_scan<<<SCAN_NB, 256>>>();
    k_scatter<<<nbE4, 256>>>(src, dst);
    k_gemm<<<nbG, 256>>>(feat, Wm);
    k_aggregate<<<nbA, 256>>>(out);
}